// round 15
// baseline (speedup 1.0000x reference)
#include <cuda_runtime.h>
#include <cuda_bf16.h>
#include <cstdint>

#define NNODES  100000
#define NEDGES  1600000
#define NGRAPHS 64
#define DIM     128
#define NCLS    10
#define SCAN_B  1024
#define NBLK    ((NNODES + SCAN_B - 1) / SCAN_B)   // 98
#define PB      136                                // smem pitch in bf16 (272B rows)
#define NBUCK   64

// ---------------- persistent device scratch ----------------
__device__ int   g_idx64;
__device__ int   g_deg_out[NNODES];
__device__ int   g_deg_in[NNODES];
__device__ int   g_fill[NNODES];
__device__ int   g_rowptr[NNODES + 1];
__device__ int   g_csr[NEDGES];
__device__ int   g_bsum[NBLK];
__device__ int   g_boff[128];
__device__ __align__(16) __nv_bfloat16 g_bufAh[(size_t)NNODES * DIM];  // layer-1 GEMM out
__device__ __align__(16) __nv_bfloat16 g_bufBh[(size_t)NNODES * DIM];  // fused spmm+gemm2 out
__device__ __align__(16) __nv_bfloat16 g_Whi[2][DIM * DIM];  // W transposed [n][k], hi
__device__ __align__(16) __nv_bfloat16 g_Wlo[2][DIM * DIM];  // W transposed [n][k], lo
__device__ float g_gsumB[NBUCK * NGRAPHS * DIM];   // bucketed partial sums (zeroed by reduce)
__device__ float g_gsum[NGRAPHS * DIM];
__device__ int   g_gcnt[NGRAPHS];

// ---------------- helpers ----------------
__device__ __forceinline__ int ldidx(const void* p, int i, bool w64) {
    if (w64) return (int)__ldg(((const long long*)p) + i);
    return __ldg(((const int*)p) + i);
}

__device__ __forceinline__ void mma16816(float* c, const uint32_t* a, uint32_t b0, uint32_t b1) {
    asm volatile(
        "mma.sync.aligned.m16n8k16.row.col.f32.bf16.bf16.f32 "
        "{%0,%1,%2,%3}, {%4,%5,%6,%7}, {%8,%9}, {%0,%1,%2,%3};"
        : "+f"(c[0]), "+f"(c[1]), "+f"(c[2]), "+f"(c[3])
        : "r"(a[0]), "r"(a[1]), "r"(a[2]), "r"(a[3]), "r"(b0), "r"(b1));
}

__device__ __forceinline__ void ldm_x4(uint32_t* r, uint32_t saddr) {
    asm volatile("ldmatrix.sync.aligned.m8n8.x4.shared.b16 {%0,%1,%2,%3}, [%4];"
                 : "=r"(r[0]), "=r"(r[1]), "=r"(r[2]), "=r"(r[3]) : "r"(saddr));
}

__device__ __forceinline__ uint32_t smem_u32(const void* p) {
    uint32_t a;
    asm("{ .reg .u64 t; cvta.to.shared.u64 t, %1; cvt.u32.u64 %0, t; }" : "=r"(a) : "l"(p));
    return a;
}

__device__ __forceinline__ uint32_t bf2_pack(float a, float b) {
    __nv_bfloat162 h;
    h.x = __float2bfloat16(a);
    h.y = __float2bfloat16(b);
    return *(uint32_t*)&h;
}

// accumulate 4 bf16 (one uint2) into a float4
__device__ __forceinline__ void bfacc(float4& a, uint2 u) {
    a.x += __uint_as_float(u.x << 16);
    a.y += __uint_as_float(u.x & 0xffff0000u);
    a.z += __uint_as_float(u.y << 16);
    a.w += __uint_as_float(u.y & 0xffff0000u);
}

// gather-sum one CSR row (bf16 rows of T, lane covers cols lane*4..+3)
__device__ __forceinline__ float4 gather_row(const __nv_bfloat16* __restrict__ T,
                                             int beg, int end, int lane) {
    float4 acc0 = make_float4(0.f, 0.f, 0.f, 0.f);
    float4 acc1 = make_float4(0.f, 0.f, 0.f, 0.f);
    int e = beg;
    for (; e + 8 <= end; e += 8) {
        int s0 = g_csr[e],     s1 = g_csr[e + 1], s2 = g_csr[e + 2], s3 = g_csr[e + 3];
        int s4 = g_csr[e + 4], s5 = g_csr[e + 5], s6 = g_csr[e + 6], s7 = g_csr[e + 7];
        uint2 u0 = __ldg((const uint2*)(T + (long)s0 * 128 + lane * 4));
        uint2 u1 = __ldg((const uint2*)(T + (long)s1 * 128 + lane * 4));
        uint2 u2 = __ldg((const uint2*)(T + (long)s2 * 128 + lane * 4));
        uint2 u3 = __ldg((const uint2*)(T + (long)s3 * 128 + lane * 4));
        uint2 u4 = __ldg((const uint2*)(T + (long)s4 * 128 + lane * 4));
        uint2 u5 = __ldg((const uint2*)(T + (long)s5 * 128 + lane * 4));
        uint2 u6 = __ldg((const uint2*)(T + (long)s6 * 128 + lane * 4));
        uint2 u7 = __ldg((const uint2*)(T + (long)s7 * 128 + lane * 4));
        bfacc(acc0, u0); bfacc(acc0, u1); bfacc(acc0, u2); bfacc(acc0, u3);
        bfacc(acc1, u4); bfacc(acc1, u5); bfacc(acc1, u6); bfacc(acc1, u7);
    }
    for (; e + 4 <= end; e += 4) {
        int s0 = g_csr[e], s1 = g_csr[e + 1], s2 = g_csr[e + 2], s3 = g_csr[e + 3];
        uint2 u0 = __ldg((const uint2*)(T + (long)s0 * 128 + lane * 4));
        uint2 u1 = __ldg((const uint2*)(T + (long)s1 * 128 + lane * 4));
        uint2 u2 = __ldg((const uint2*)(T + (long)s2 * 128 + lane * 4));
        uint2 u3 = __ldg((const uint2*)(T + (long)s3 * 128 + lane * 4));
        bfacc(acc0, u0); bfacc(acc0, u1); bfacc(acc0, u2); bfacc(acc0, u3);
    }
    for (; e < end; e++) {
        int s = g_csr[e];
        uint2 u = __ldg((const uint2*)(T + (long)s * 128 + lane * 4));
        bfacc(acc1, u);
    }
    return make_float4(acc0.x + acc1.x, acc0.y + acc1.y, acc0.z + acc1.z, acc0.w + acc1.w);
}

// ---------------- 0. one-time W conversion: W[k][n] -> Whi/Wlo[n][k] bf16 ----------------
__global__ void k_prepW(const float* __restrict__ W1, const float* __restrict__ W2) {
    int idx = blockIdx.x * blockDim.x + threadIdx.x;   // 0..32767
    int m = idx >> 14;
    int r = idx & 16383;
    int n = r & 127;
    int k = r >> 7;
    const float* W = m ? W2 : W1;
    float w = __ldg(W + k * 128 + n);
    __nv_bfloat16 hi = __float2bfloat16(w);
    g_Whi[m][n * 128 + k] = hi;
    g_Wlo[m][n * 128 + k] = __float2bfloat16(w - __bfloat162float(hi));
}

// ---------------- 1+2. zero scratch (block 0 also does dtype detection) ----------------
__global__ void k_zero(const void* src) {
    if (blockIdx.x == 0) {
        __shared__ int any_nonzero;
        if (threadIdx.x == 0) any_nonzero = 0;
        __syncthreads();
        const unsigned int* p = (const unsigned int*)src;
        if (p[2 * threadIdx.x + 1] != 0u) atomicOr(&any_nonzero, 1);
        __syncthreads();
        if (threadIdx.x == 0) g_idx64 = (any_nonzero == 0) ? 1 : 0;
    }
    int i = blockIdx.x * blockDim.x + threadIdx.x;
    int stride = gridDim.x * blockDim.x;
    for (int j = i; j < NNODES; j += stride) {
        g_deg_out[j] = 0;
        g_deg_in[j]  = 0;
    }
    if (i < NGRAPHS) g_gcnt[i] = 0;
}

// ---------------- 3. degree + graph-count histograms (4 edges/thread, MLP) ----------------
__global__ void k_degrees(const void* src, const void* dst, const void* gids) {
    bool w64 = (g_idx64 != 0);
    int t = blockIdx.x * blockDim.x + threadIdx.x;
    int e0 = t * 4;
    if (e0 + 4 <= NEDGES) {
        int s0, s1, s2, s3, d0, d1, d2, d3;
        if (w64) {
            const long long* sp = (const long long*)src + e0;
            const long long* dp = (const long long*)dst + e0;
            longlong2 a = __ldg((const longlong2*)sp);
            longlong2 b = __ldg((const longlong2*)(sp + 2));
            longlong2 c = __ldg((const longlong2*)dp);
            longlong2 d = __ldg((const longlong2*)(dp + 2));
            s0 = (int)a.x; s1 = (int)a.y; s2 = (int)b.x; s3 = (int)b.y;
            d0 = (int)c.x; d1 = (int)c.y; d2 = (int)d.x; d3 = (int)d.y;
        } else {
            int4 a = __ldg((const int4*)((const int*)src + e0));
            int4 c = __ldg((const int4*)((const int*)dst + e0));
            s0 = a.x; s1 = a.y; s2 = a.z; s3 = a.w;
            d0 = c.x; d1 = c.y; d2 = c.z; d3 = c.w;
        }
        atomicAdd(&g_deg_out[s0], 1);
        atomicAdd(&g_deg_out[s1], 1);
        atomicAdd(&g_deg_out[s2], 1);
        atomicAdd(&g_deg_out[s3], 1);
        atomicAdd(&g_deg_in[d0], 1);
        atomicAdd(&g_deg_in[d1], 1);
        atomicAdd(&g_deg_in[d2], 1);
        atomicAdd(&g_deg_in[d3], 1);
    } else {
        for (int e = e0; e < NEDGES; e++) {
            atomicAdd(&g_deg_out[ldidx(src, e, w64)], 1);
            atomicAdd(&g_deg_in[ldidx(dst, e, w64)], 1);
        }
    }
    if (t < NNODES) {
        int g = ldidx(gids, t, w64);
        atomicAdd(&g_gcnt[g], 1);
    }
}

// ---------------- 4-6. coalesced 3-phase exclusive scan ----------------
__global__ void __launch_bounds__(SCAN_B) k_scanA() {
    __shared__ int sh[SCAN_B];
    int tid = threadIdx.x;
    int i = blockIdx.x * SCAN_B + tid;
    int v = (i < NNODES) ? g_deg_in[i] : 0;
    sh[tid] = v;
    __syncthreads();
    for (int off = 1; off < SCAN_B; off <<= 1) {
        int t = (tid >= off) ? sh[tid - off] : 0;
        __syncthreads();
        sh[tid] += t;
        __syncthreads();
    }
    if (i < NNODES) g_rowptr[i] = sh[tid] - v;
    if (tid == SCAN_B - 1) g_bsum[blockIdx.x] = sh[tid];
}

__global__ void k_scanB() {
    __shared__ int sh[128];
    int tid = threadIdx.x;
    int v = (tid < NBLK) ? g_bsum[tid] : 0;
    sh[tid] = v;
    __syncthreads();
    for (int off = 1; off < 128; off <<= 1) {
        int t = (tid >= off) ? sh[tid - off] : 0;
        __syncthreads();
        sh[tid] += t;
        __syncthreads();
    }
    g_boff[tid] = sh[tid] - v;
}

__global__ void __launch_bounds__(SCAN_B) k_scanC() {
    int tid = threadIdx.x;
    int i = blockIdx.x * SCAN_B + tid;
    if (i < NNODES) {
        int r = g_rowptr[i] + g_boff[blockIdx.x];
        g_rowptr[i] = r;
        g_fill[i]   = r;
    }
    if (i == 0) g_rowptr[NNODES] = NEDGES;
}

// ---------------- 7. CSR scatter ----------------
__global__ void k_scatter(const void* src, const void* dst) {
    bool w64 = (g_idx64 != 0);
    int i0 = blockIdx.x * blockDim.x + threadIdx.x;
    int stride = gridDim.x * blockDim.x;
    for (int e = i0; e < NEDGES; e += stride) {
        int d = ldidx(dst, e, w64);
        int s = ldidx(src, e, w64);
        int pos = atomicAdd(&g_fill[d], 1);
        g_csr[pos] = s;
    }
}

// ---------------- shared GEMM pieces ----------------
#define SM_AHI 0
#define SM_BHI (128 * PB)
#define SM_BLO (2 * 128 * PB)
#define GEMM_DYN_SMEM (3 * 128 * PB * 2)   // 104448 bytes -> 2 CTAs/SM

__device__ __forceinline__ void stage_W(__nv_bfloat16* sm, int tid, int layer) {
    const __nv_bfloat16* __restrict__ Wh = g_Whi[layer];
    const __nv_bfloat16* __restrict__ Wl = g_Wlo[layer];
#pragma unroll
    for (int it = 0; it < 4; it++) {
        int idx = tid + it * 512;
        int row = idx >> 4;
        int c8 = (idx & 15) * 8;
        uint4 hv = *(const uint4*)(Wh + row * 128 + c8);
        uint4 lv = *(const uint4*)(Wl + row * 128 + c8);
        *(uint4*)(sm + SM_BHI + row * PB + c8) = hv;
        *(uint4*)(sm + SM_BLO + row * PB + c8) = lv;
    }
}

// 32x32 warp-tile mainloop + bf16 epilogue to C
__device__ __forceinline__ void gemm_main(__nv_bfloat16* sm, __nv_bfloat16* __restrict__ C,
                                          int wid, int lane, int blockM, int M) {
    float acc[2][4][4];
#pragma unroll
    for (int mi = 0; mi < 2; mi++)
#pragma unroll
        for (int nt = 0; nt < 4; nt++)
#pragma unroll
            for (int j = 0; j < 4; j++) acc[mi][nt][j] = 0.0f;

    int warpRow = (wid >> 2) * 32;
    int warpCol = (wid & 3) * 32;
    int mtx  = lane >> 3;
    int lrow = lane & 7;

    uint32_t smbase = smem_u32(sm);
    uint32_t aoffElem = (uint32_t)((warpRow + lrow + (mtx & 1) * 8) * PB + (mtx >> 1) * 8);
    uint32_t boffRow  = (uint32_t)((warpCol + (mtx >> 1) * 8 + lrow) * PB + (mtx & 1) * 8);

#pragma unroll
    for (int ks = 0; ks < 8; ks++) {
        int kk = ks * 16;
        uint32_t a0[4], a1[4];
        ldm_x4(a0, smbase + (SM_AHI + aoffElem + kk) * 2);
        ldm_x4(a1, smbase + (SM_AHI + aoffElem + 16 * PB + kk) * 2);
#pragma unroll
        for (int np = 0; np < 2; np++) {
            uint32_t bhi[4], blo[4];
            uint32_t bo = boffRow + (uint32_t)(np * 16 * PB + kk);
            ldm_x4(bhi, smbase + (SM_BHI + bo) * 2);
            ldm_x4(blo, smbase + (SM_BLO + bo) * 2);
            mma16816(acc[0][2 * np],     a0, bhi[0], bhi[1]);
            mma16816(acc[0][2 * np],     a0, blo[0], blo[1]);
            mma16816(acc[0][2 * np + 1], a0, bhi[2], bhi[3]);
            mma16816(acc[0][2 * np + 1], a0, blo[2], blo[3]);
            mma16816(acc[1][2 * np],     a1, bhi[0], bhi[1]);
            mma16816(acc[1][2 * np],     a1, blo[0], blo[1]);
            mma16816(acc[1][2 * np + 1], a1, bhi[2], bhi[3]);
            mma16816(acc[1][2 * np + 1], a1, blo[2], blo[3]);
        }
    }

    int q2 = (lane & 3) * 2;
#pragma unroll
    for (int mi = 0; mi < 2; mi++) {
        int r0 = warpRow + mi * 16 + (lane >> 2);
        int growA = blockM + r0;
        int growB = growA + 8;
#pragma unroll
        for (int nt = 0; nt < 4; nt++) {
            int col = warpCol + nt * 8 + q2;
            if (growA < M) *(uint32_t*)(C + (long)growA * 128 + col) = bf2_pack(acc[mi][nt][0], acc[mi][nt][1]);
            if (growB < M) *(uint32_t*)(C + (long)growB * 128 + col) = bf2_pack(acc[mi][nt][2], acc[mi][nt][3]);
        }
    }
}

// ---------------- 8. layer-1 GEMM: bufAh = bf16((h*rs_out) @ W1) ----------------
__global__ void __launch_bounds__(512, 2) k_mmagemm1(const float* __restrict__ Aext, int M) {
    extern __shared__ __align__(16) __nv_bfloat16 sm[];
    int tid = threadIdx.x;
    int blockM = blockIdx.x * 128;
#pragma unroll
    for (int it = 0; it < 8; it++) {
        int idx4 = tid + it * 512;
        int row = idx4 >> 5;
        int c4 = (idx4 & 31) * 4;
        int grow = blockM + row;
        float4 v = make_float4(0.f, 0.f, 0.f, 0.f);
        if (grow < M) {
            v = *(const float4*)(Aext + (long)grow * 128 + c4);
            float sc = rsqrtf((float)max(g_deg_out[grow], 1));
            v.x *= sc; v.y *= sc; v.z *= sc; v.w *= sc;
        }
        uint2 hu = make_uint2(bf2_pack(v.x, v.y), bf2_pack(v.z, v.w));
        *(uint2*)(sm + SM_AHI + row * PB + c4) = hu;
    }
    stage_W(sm, tid, 0);
    __syncthreads();
    gemm_main(sm, g_bufAh, tid >> 5, tid & 31, blockM, M);
}

// ---------------- 9. FUSED spmm1 + layer-2 GEMM: bufBh = bf16(agg-epilogue(bufAh) @ W2) ----------------
__global__ void __launch_bounds__(512, 2) k_spmmgemm(const float* __restrict__ bias, int M) {
    extern __shared__ __align__(16) __nv_bfloat16 sm[];
    int tid = threadIdx.x;
    int wid = tid >> 5;
    int lane = tid & 31;
    int blockM = blockIdx.x * 128;

    // phase 1: warp w aggregates rows w*8 .. w*8+7 into the A smem tile
    {
        float4 b = *(const float4*)(bias + lane * 4);
#pragma unroll
        for (int r = 0; r < 8; r++) {
            int row = wid * 8 + r;
            int node = blockM + row;
            uint2 p = make_uint2(0u, 0u);
            if (node < M) {
                int beg = g_rowptr[node], end = g_rowptr[node + 1];
                float4 acc = gather_row(g_bufAh, beg, end, lane);
                float ri = rsqrtf((float)max(end - beg, 1));
                float ro = rsqrtf((float)max(g_deg_out[node], 1));
                float ox = fmaxf(fmaf(acc.x, ri, b.x), 0.f) * ro;
                float oy = fmaxf(fmaf(acc.y, ri, b.y), 0.f) * ro;
                float oz = fmaxf(fmaf(acc.z, ri, b.z), 0.f) * ro;
                float ow = fmaxf(fmaf(acc.w, ri, b.w), 0.f) * ro;
                p = make_uint2(bf2_pack(ox, oy), bf2_pack(oz, ow));
            }
            *(uint2*)(sm + SM_AHI + row * PB + lane * 4) = p;
        }
    }
    stage_W(sm, tid, 1);
    __syncthreads();
    gemm_main(sm, g_bufBh, wid, lane, blockM, M);   // OUTPUT to bufBh (bufAh still being read by peers)
}

// ---------------- 10. final SpMM (gathers bufBh) + per-graph readout ----------------
__global__ void __launch_bounds__(256) k_spmm_final(const float* __restrict__ bias,
                                                    const void* __restrict__ gids) {
    __shared__ float srow[8][DIM];
    __shared__ int   sgid[8];

    int warp = (blockIdx.x * blockDim.x + threadIdx.x) >> 5;
    int lane = threadIdx.x & 31;
    int w = (threadIdx.x >> 5);
    bool active = (warp < NNODES);

    float4 o = make_float4(0.f, 0.f, 0.f, 0.f);
    if (active) {
        int beg = g_rowptr[warp], end = g_rowptr[warp + 1];
        float4 acc = gather_row(g_bufBh, beg, end, lane);
        float ri = rsqrtf((float)max(end - beg, 1));
        float4 b = *(const float4*)(bias + lane * 4);
        o.x = fmaxf(fmaf(acc.x, ri, b.x), 0.f);
        o.y = fmaxf(fmaf(acc.y, ri, b.y), 0.f);
        o.z = fmaxf(fmaf(acc.z, ri, b.z), 0.f);
        o.w = fmaxf(fmaf(acc.w, ri, b.w), 0.f);
    }

    *(float4*)&srow[w][lane * 4] = o;
    if (lane == 0) {
        bool w64 = (g_idx64 != 0);
        sgid[w] = active ? ldidx(gids, warp, w64) : -1;
    }
    __syncthreads();
    if (threadIdx.x < DIM) {
        int col = threadIdx.x;
        float* bucket = g_gsumB + (blockIdx.x & (NBUCK - 1)) * (NGRAPHS * DIM);
        int cur = sgid[0];
        float acc = srow[0][col];
#pragma unroll
        for (int r = 1; r < 8; r++) {
            int gr = sgid[r];
            float v = srow[r][col];
            if (gr == cur) {
                acc += v;
            } else {
                if (cur >= 0) atomicAdd(&bucket[cur * DIM + col], acc);
                cur = gr; acc = v;
            }
        }
        if (cur >= 0) atomicAdd(&bucket[cur * DIM + col], acc);
    }
}

// ---------------- 11. fold buckets -> g_gsum, then re-zero buckets ----------------
__global__ void k_gsum_reduce() {
    int i = blockIdx.x * blockDim.x + threadIdx.x;
    if (i < NGRAPHS * DIM) {
        float s = 0.f;
#pragma unroll 8
        for (int b = 0; b < NBUCK; b++) {
            s += g_gsumB[b * (NGRAPHS * DIM) + i];
            g_gsumB[b * (NGRAPHS * DIM) + i] = 0.0f;
        }
        g_gsum[i] = s;
    }
}

// ---------------- 12. classifier head ----------------
__global__ void k_final(const float* __restrict__ Wc, const float* __restrict__ bc,
                        float* __restrict__ out) {
    int t = threadIdx.x;
    if (t >= NGRAPHS * NCLS) return;
    int g = t / NCLS, c = t % NCLS;
    float s = 0.f;
#pragma unroll 8
    for (int k = 0; k < 128; k++) s = fmaf(g_gsum[g * 128 + k], Wc[k * NCLS + c], s);
    float cnt = (float)max(g_gcnt[g], 1);
    out[t] = s / cnt + bc[c];
}

// ---------------- launch ----------------
extern "C" void kernel_launch(void* const* d_in, const int* in_sizes, int n_in,
                              void* d_out, int out_size) {
    const float* h   = (const float*)d_in[0];
    const void*  src = d_in[1];
    const void*  dst = d_in[2];
    const void*  gid = d_in[3];
    const float* W1  = (const float*)d_in[4];
    const float* b1  = (const float*)d_in[5];
    const float* W2  = (const float*)d_in[6];
    const float* b2  = (const float*)d_in[7];
    const float* Wc  = (const float*)d_in[8];
    const float* bc  = (const float*)d_in[9];
    float* out = (float*)d_out;

    const int M = NNODES;
    int gemmGrid = (M + 127) / 128;
    int spmmGrid = (M * 32 + 255) / 256;
    int degGrid  = (NEDGES / 4 + 255) / 256;   // 1563

    cudaFuncSetAttribute(k_mmagemm1, cudaFuncAttributeMaxDynamicSharedMemorySize, GEMM_DYN_SMEM);
    cudaFuncSetAttribute(k_spmmgemm, cudaFuncAttributeMaxDynamicSharedMemorySize, GEMM_DYN_SMEM);

    k_prepW<<<128, 256>>>(W1, W2);                               // 1
    k_zero<<<512, 256>>>(src);                                   // 2  (incl. dtype detect)
    k_degrees<<<degGrid, 256>>>(src, dst, gid);                  // 3
    k_mmagemm1<<<gemmGrid, 512, GEMM_DYN_SMEM>>>(h, M);          // 4  <- profiled slot
    k_scanA<<<NBLK, SCAN_B>>>();                                 // 5
    k_scanB<<<1, 128>>>();                                       // 6
    k_scanC<<<NBLK, SCAN_B>>>();                                 // 7
    k_scatter<<<1184, 256>>>(src, dst);                          // 8
    k_spmmgemm<<<gemmGrid, 512, GEMM_DYN_SMEM>>>(b1, M);         // 9  fused spmm1+gemm2
    k_spmm_final<<<spmmGrid, 256>>>(b2, gid);                    // 10
    k_gsum_reduce<<<32, 256>>>();                                // 11
    k_final<<<1, NGRAPHS * NCLS>>>(Wc, bc, out);                 // 12
}

// round 16
// speedup vs baseline: 1.0548x; 1.0548x over previous
#include <cuda_runtime.h>
#include <cuda_bf16.h>
#include <cstdint>

#define NNODES  100000
#define NEDGES  1600000
#define NGRAPHS 64
#define DIM     128
#define NCLS    10
#define SCAN_B  1024
#define NBLK    ((NNODES + SCAN_B - 1) / SCAN_B)   // 98
#define PB      136                                // smem pitch in bf16 (272B rows)
#define NBUCK   64

// ---------------- persistent device scratch ----------------
__device__ int   g_idx64;
__device__ int   g_scan_done;                      // last-block counter (self-resetting)
__device__ int   g_deg_out[NNODES];
__device__ int   g_deg_in[NNODES];
__device__ int   g_fill[NNODES];
__device__ int   g_rowptr[NNODES + 1];
__device__ int   g_csr[NEDGES];
__device__ int   g_bsum[NBLK];
__device__ int   g_boff[128];
__device__ __align__(16) __nv_bfloat16 g_bufAh[(size_t)NNODES * DIM];  // GEMM out (bf16)
__device__ __align__(16) __nv_bfloat16 g_bufBh[(size_t)NNODES * DIM];  // spmm1 out (bf16)
__device__ __align__(16) __nv_bfloat16 g_Whi[2][DIM * DIM];  // W transposed [n][k], hi
__device__ __align__(16) __nv_bfloat16 g_Wlo[2][DIM * DIM];  // W transposed [n][k], lo
__device__ float g_gsumB[NBUCK * NGRAPHS * DIM];   // bucketed partial sums (zeroed by reduce)
__device__ float g_gsum[NGRAPHS * DIM];
__device__ int   g_gcnt[NGRAPHS];

// ---------------- helpers ----------------
__device__ __forceinline__ int ldidx(const void* p, int i, bool w64) {
    if (w64) return (int)__ldg(((const long long*)p) + i);
    return __ldg(((const int*)p) + i);
}

__device__ __forceinline__ void mma16816(float* c, const uint32_t* a, uint32_t b0, uint32_t b1) {
    asm volatile(
        "mma.sync.aligned.m16n8k16.row.col.f32.bf16.bf16.f32 "
        "{%0,%1,%2,%3}, {%4,%5,%6,%7}, {%8,%9}, {%0,%1,%2,%3};"
        : "+f"(c[0]), "+f"(c[1]), "+f"(c[2]), "+f"(c[3])
        : "r"(a[0]), "r"(a[1]), "r"(a[2]), "r"(a[3]), "r"(b0), "r"(b1));
}

__device__ __forceinline__ void ldm_x4(uint32_t* r, uint32_t saddr) {
    asm volatile("ldmatrix.sync.aligned.m8n8.x4.shared.b16 {%0,%1,%2,%3}, [%4];"
                 : "=r"(r[0]), "=r"(r[1]), "=r"(r[2]), "=r"(r[3]) : "r"(saddr));
}

__device__ __forceinline__ uint32_t smem_u32(const void* p) {
    uint32_t a;
    asm("{ .reg .u64 t; cvta.to.shared.u64 t, %1; cvt.u32.u64 %0, t; }" : "=r"(a) : "l"(p));
    return a;
}

__device__ __forceinline__ uint32_t bf2_pack(float a, float b) {
    __nv_bfloat162 h;
    h.x = __float2bfloat16(a);
    h.y = __float2bfloat16(b);
    return *(uint32_t*)&h;
}

// accumulate 4 bf16 (one uint2) into a float4
__device__ __forceinline__ void bfacc(float4& a, uint2 u) {
    a.x += __uint_as_float(u.x << 16);
    a.y += __uint_as_float(u.x & 0xffff0000u);
    a.z += __uint_as_float(u.y << 16);
    a.w += __uint_as_float(u.y & 0xffff0000u);
}

// ---------------- 1. zero scratch + dtype detect (block 0) + prepW (blocks 0-127) ----------------
__global__ void k_zero(const void* src, const float* __restrict__ W1,
                       const float* __restrict__ W2) {
    if (blockIdx.x == 0) {
        __shared__ int any_nonzero;
        if (threadIdx.x == 0) any_nonzero = 0;
        __syncthreads();
        const unsigned int* p = (const unsigned int*)src;
        if (p[2 * threadIdx.x + 1] != 0u) atomicOr(&any_nonzero, 1);
        __syncthreads();
        if (threadIdx.x == 0) g_idx64 = (any_nonzero == 0) ? 1 : 0;
    }
    // prepW: 128 blocks x 256 threads cover 2*128*128 = 32768 elements
    if (blockIdx.x < 128) {
        int idx = blockIdx.x * 256 + threadIdx.x;
        int m = idx >> 14;
        int r = idx & 16383;
        int n = r & 127;               // consecutive n -> coalesced W read
        int k = r >> 7;
        const float* W = m ? W2 : W1;
        float w = __ldg(W + k * 128 + n);
        __nv_bfloat16 hi = __float2bfloat16(w);
        g_Whi[m][n * 128 + k] = hi;
        g_Wlo[m][n * 128 + k] = __float2bfloat16(w - __bfloat162float(hi));
    }
    int i = blockIdx.x * blockDim.x + threadIdx.x;
    int stride = gridDim.x * blockDim.x;
    for (int j = i; j < NNODES; j += stride) {
        g_deg_out[j] = 0;
        g_deg_in[j]  = 0;
    }
    if (i < NGRAPHS) g_gcnt[i] = 0;
}

// ---------------- 2. degree + graph-count histograms (4 edges/thread, MLP) ----------------
__global__ void k_degrees(const void* src, const void* dst, const void* gids) {
    bool w64 = (g_idx64 != 0);
    int t = blockIdx.x * blockDim.x + threadIdx.x;
    int e0 = t * 4;
    if (e0 + 4 <= NEDGES) {
        int s0, s1, s2, s3, d0, d1, d2, d3;
        if (w64) {
            const long long* sp = (const long long*)src + e0;
            const long long* dp = (const long long*)dst + e0;
            longlong2 a = __ldg((const longlong2*)sp);
            longlong2 b = __ldg((const longlong2*)(sp + 2));
            longlong2 c = __ldg((const longlong2*)dp);
            longlong2 d = __ldg((const longlong2*)(dp + 2));
            s0 = (int)a.x; s1 = (int)a.y; s2 = (int)b.x; s3 = (int)b.y;
            d0 = (int)c.x; d1 = (int)c.y; d2 = (int)d.x; d3 = (int)d.y;
        } else {
            int4 a = __ldg((const int4*)((const int*)src + e0));
            int4 c = __ldg((const int4*)((const int*)dst + e0));
            s0 = a.x; s1 = a.y; s2 = a.z; s3 = a.w;
            d0 = c.x; d1 = c.y; d2 = c.z; d3 = c.w;
        }
        atomicAdd(&g_deg_out[s0], 1);
        atomicAdd(&g_deg_out[s1], 1);
        atomicAdd(&g_deg_out[s2], 1);
        atomicAdd(&g_deg_out[s3], 1);
        atomicAdd(&g_deg_in[d0], 1);
        atomicAdd(&g_deg_in[d1], 1);
        atomicAdd(&g_deg_in[d2], 1);
        atomicAdd(&g_deg_in[d3], 1);
    } else {
        for (int e = e0; e < NEDGES; e++) {
            atomicAdd(&g_deg_out[ldidx(src, e, w64)], 1);
            atomicAdd(&g_deg_in[ldidx(dst, e, w64)], 1);
        }
    }
    if (t < NNODES) {
        int g = ldidx(gids, t, w64);
        atomicAdd(&g_gcnt[g], 1);
    }
}

// ---------------- 3-4. scan: block-local prefix + last-block computes block offsets ----------------
__global__ void __launch_bounds__(SCAN_B) k_scanA() {
    __shared__ int sh[SCAN_B];
    __shared__ int isLast;
    int tid = threadIdx.x;
    int i = blockIdx.x * SCAN_B + tid;
    int v = (i < NNODES) ? g_deg_in[i] : 0;
    sh[tid] = v;
    __syncthreads();
    for (int off = 1; off < SCAN_B; off <<= 1) {
        int t = (tid >= off) ? sh[tid - off] : 0;
        __syncthreads();
        sh[tid] += t;
        __syncthreads();
    }
    if (i < NNODES) g_rowptr[i] = sh[tid] - v;   // block-local exclusive prefix
    if (tid == SCAN_B - 1) g_bsum[blockIdx.x] = sh[tid];
    __threadfence();
    if (tid == 0) {
        int c = atomicAdd(&g_scan_done, 1);
        isLast = (c == gridDim.x - 1);
    }
    __syncthreads();
    if (isLast) {
        // 128-entry exclusive scan of g_bsum -> g_boff (threads 0-127 active)
        int bv = 0;
        if (tid < 128) bv = (tid < NBLK) ? g_bsum[tid] : 0;
        sh[tid] = bv;
        __syncthreads();
        for (int off = 1; off < 128; off <<= 1) {
            int t = (tid >= off && tid < 128) ? sh[tid - off] : 0;
            __syncthreads();
            if (tid < 128) sh[tid] += t;
            __syncthreads();
        }
        if (tid < 128) g_boff[tid] = sh[tid] - bv;
        if (tid == 0) g_scan_done = 0;           // reset for next invocation
    }
}

__global__ void __launch_bounds__(SCAN_B) k_scanC() {
    int tid = threadIdx.x;
    int i = blockIdx.x * SCAN_B + tid;
    if (i < NNODES) {
        int r = g_rowptr[i] + g_boff[blockIdx.x];
        g_rowptr[i] = r;
        g_fill[i]   = r;
    }
    if (i == 0) g_rowptr[NNODES] = NEDGES;
}

// ---------------- 5. CSR scatter ----------------
__global__ void k_scatter(const void* src, const void* dst) {
    bool w64 = (g_idx64 != 0);
    int i0 = blockIdx.x * blockDim.x + threadIdx.x;
    int stride = gridDim.x * blockDim.x;
    for (int e = i0; e < NEDGES; e += stride) {
        int d = ldidx(dst, e, w64);
        int s = ldidx(src, e, w64);
        int pos = atomicAdd(&g_fill[d], 1);
        g_csr[pos] = s;
    }
}

// ---------------- 6. mma.sync 2-term split GEMM (32x32 warp tiles, 2 CTA/SM) ----------------
// D = Ahi*(Whi + Wlo); W pre-converted & transposed -> coalesced staging.
#define SM_AHI 0
#define SM_BHI (128 * PB)
#define SM_BLO (2 * 128 * PB)
#define GEMM_DYN_SMEM (3 * 128 * PB * 2)   // 104448 bytes -> 2 CTAs/SM

template <int LAYER>
__global__ void __launch_bounds__(512, 2) k_mmagemm(const float* __restrict__ Aext, int M) {
    extern __shared__ __align__(16) __nv_bfloat16 sm[];

    __nv_bfloat16* __restrict__ C = g_bufAh;

    int tid = threadIdx.x;
    int wid = tid >> 5;
    int lane = tid & 31;
    int blockM = blockIdx.x * 128;

    // ---- stage A ----
    if (LAYER == 1) {
#pragma unroll
        for (int it = 0; it < 8; it++) {
            int idx4 = tid + it * 512;
            int row = idx4 >> 5;
            int c4 = (idx4 & 31) * 4;
            int grow = blockM + row;
            float4 v = make_float4(0.f, 0.f, 0.f, 0.f);
            if (grow < M) {
                v = *(const float4*)(Aext + (long)grow * 128 + c4);
                float sc = rsqrtf((float)max(g_deg_out[grow], 1));
                v.x *= sc; v.y *= sc; v.z *= sc; v.w *= sc;
            }
            uint2 hu = make_uint2(bf2_pack(v.x, v.y), bf2_pack(v.z, v.w));
            *(uint2*)(sm + SM_AHI + row * PB + c4) = hu;
        }
    } else {
#pragma unroll
        for (int it = 0; it < 4; it++) {
            int idx = tid + it * 512;
            int row = idx >> 4;
            int c8 = (idx & 15) * 8;
            int grow = blockM + row;
            uint4 v = make_uint4(0u, 0u, 0u, 0u);
            if (grow < M) v = *(const uint4*)(g_bufBh + (long)grow * 128 + c8);
            *(uint4*)(sm + SM_AHI + row * PB + c8) = v;
        }
    }
    // ---- stage W hi/lo: coalesced uint4 copies ----
    {
        const __nv_bfloat16* __restrict__ Wh = g_Whi[LAYER - 1];
        const __nv_bfloat16* __restrict__ Wl = g_Wlo[LAYER - 1];
#pragma unroll
        for (int it = 0; it < 4; it++) {
            int idx = tid + it * 512;
            int row = idx >> 4;
            int c8 = (idx & 15) * 8;
            uint4 hv = *(const uint4*)(Wh + row * 128 + c8);
            uint4 lv = *(const uint4*)(Wl + row * 128 + c8);
            *(uint4*)(sm + SM_BHI + row * PB + c8) = hv;
            *(uint4*)(sm + SM_BLO + row * PB + c8) = lv;
        }
    }
    __syncthreads();

    float acc[2][4][4];
#pragma unroll
    for (int mi = 0; mi < 2; mi++)
#pragma unroll
        for (int nt = 0; nt < 4; nt++)
#pragma unroll
            for (int j = 0; j < 4; j++) acc[mi][nt][j] = 0.0f;

    int warpRow = (wid >> 2) * 32;
    int warpCol = (wid & 3) * 32;
    int mtx  = lane >> 3;
    int lrow = lane & 7;

    uint32_t smbase = smem_u32(sm);
    uint32_t aoffElem = (uint32_t)((warpRow + lrow + (mtx & 1) * 8) * PB + (mtx >> 1) * 8);
    uint32_t boffRow  = (uint32_t)((warpCol + (mtx >> 1) * 8 + lrow) * PB + (mtx & 1) * 8);

#pragma unroll
    for (int ks = 0; ks < 8; ks++) {
        int kk = ks * 16;
        uint32_t a0[4], a1[4];
        ldm_x4(a0, smbase + (SM_AHI + aoffElem + kk) * 2);
        ldm_x4(a1, smbase + (SM_AHI + aoffElem + 16 * PB + kk) * 2);
#pragma unroll
        for (int np = 0; np < 2; np++) {
            uint32_t bhi[4], blo[4];
            uint32_t bo = boffRow + (uint32_t)(np * 16 * PB + kk);
            ldm_x4(bhi, smbase + (SM_BHI + bo) * 2);
            ldm_x4(blo, smbase + (SM_BLO + bo) * 2);
            mma16816(acc[0][2 * np],     a0, bhi[0], bhi[1]);
            mma16816(acc[0][2 * np],     a0, blo[0], blo[1]);
            mma16816(acc[0][2 * np + 1], a0, bhi[2], bhi[3]);
            mma16816(acc[0][2 * np + 1], a0, blo[2], blo[3]);
            mma16816(acc[1][2 * np],     a1, bhi[0], bhi[1]);
            mma16816(acc[1][2 * np],     a1, blo[0], blo[1]);
            mma16816(acc[1][2 * np + 1], a1, bhi[2], bhi[3]);
            mma16816(acc[1][2 * np + 1], a1, blo[2], blo[3]);
        }
    }

    // ---- epilogue: bf16x2 packed stores ----
    int q2 = (lane & 3) * 2;
#pragma unroll
    for (int mi = 0; mi < 2; mi++) {
        int r0 = warpRow + mi * 16 + (lane >> 2);
        int growA = blockM + r0;
        int growB = growA + 8;
#pragma unroll
        for (int nt = 0; nt < 4; nt++) {
            int col = warpCol + nt * 8 + q2;
            if (growA < M) *(uint32_t*)(C + (long)growA * 128 + col) = bf2_pack(acc[mi][nt][0], acc[mi][nt][1]);
            if (growB < M) *(uint32_t*)(C + (long)growB * 128 + col) = bf2_pack(acc[mi][nt][2], acc[mi][nt][3]);
        }
    }
}

// ---------------- 7. SpMM (warp per dst row, bf16 gather) ----------------
// FINAL: CTA segmented reduction over sorted gids + 64-way bucketed atomics.
template <bool FINAL>
__global__ void __launch_bounds__(256) k_spmm(const float* __restrict__ bias,
                                              const void* __restrict__ gids) {
    __shared__ float srow[8][DIM];
    __shared__ int   sgid[8];

    int warp = (blockIdx.x * blockDim.x + threadIdx.x) >> 5;
    int lane = threadIdx.x & 31;
    int w = (threadIdx.x >> 5);
    bool active = (warp < NNODES);

    float4 o = make_float4(0.f, 0.f, 0.f, 0.f);
    if (active) {
        int beg = g_rowptr[warp], end = g_rowptr[warp + 1];
        const __nv_bfloat16* __restrict__ T = g_bufAh;
        float4 acc0 = make_float4(0.f, 0.f, 0.f, 0.f);
        float4 acc1 = make_float4(0.f, 0.f, 0.f, 0.f);
        int e = beg;
        for (; e + 8 <= end; e += 8) {
            int s0 = g_csr[e],     s1 = g_csr[e + 1], s2 = g_csr[e + 2], s3 = g_csr[e + 3];
            int s4 = g_csr[e + 4], s5 = g_csr[e + 5], s6 = g_csr[e + 6], s7 = g_csr[e + 7];
            uint2 u0 = __ldg((const uint2*)(T + (long)s0 * 128 + lane * 4));
            uint2 u1 = __ldg((const uint2*)(T + (long)s1 * 128 + lane * 4));
            uint2 u2 = __ldg((const uint2*)(T + (long)s2 * 128 + lane * 4));
            uint2 u3 = __ldg((const uint2*)(T + (long)s3 * 128 + lane * 4));
            uint2 u4 = __ldg((const uint2*)(T + (long)s4 * 128 + lane * 4));
            uint2 u5 = __ldg((const uint2*)(T + (long)s5 * 128 + lane * 4));
            uint2 u6 = __ldg((const uint2*)(T + (long)s6 * 128 + lane * 4));
            uint2 u7 = __ldg((const uint2*)(T + (long)s7 * 128 + lane * 4));
            bfacc(acc0, u0); bfacc(acc0, u1); bfacc(acc0, u2); bfacc(acc0, u3);
            bfacc(acc1, u4); bfacc(acc1, u5); bfacc(acc1, u6); bfacc(acc1, u7);
        }
        for (; e + 4 <= end; e += 4) {
            int s0 = g_csr[e], s1 = g_csr[e + 1], s2 = g_csr[e + 2], s3 = g_csr[e + 3];
            uint2 u0 = __ldg((const uint2*)(T + (long)s0 * 128 + lane * 4));
            uint2 u1 = __ldg((const uint2*)(T + (long)s1 * 128 + lane * 4));
            uint2 u2 = __ldg((const uint2*)(T + (long)s2 * 128 + lane * 4));
            uint2 u3 = __ldg((const uint2*)(T + (long)s3 * 128 + lane * 4));
            bfacc(acc0, u0); bfacc(acc0, u1); bfacc(acc0, u2); bfacc(acc0, u3);
        }
        for (; e < end; e++) {
            int s = g_csr[e];
            uint2 u = __ldg((const uint2*)(T + (long)s * 128 + lane * 4));
            bfacc(acc1, u);
        }
        float4 acc = make_float4(acc0.x + acc1.x, acc0.y + acc1.y,
                                 acc0.z + acc1.z, acc0.w + acc1.w);
        float ri = rsqrtf((float)max(end - beg, 1));
        float4 b = *(const float4*)(bias + lane * 4);
        if (!FINAL) {
            float ro = rsqrtf((float)max(g_deg_out[warp], 1));
            o.x = fmaxf(fmaf(acc.x, ri, b.x), 0.f) * ro;
            o.y = fmaxf(fmaf(acc.y, ri, b.y), 0.f) * ro;
            o.z = fmaxf(fmaf(acc.z, ri, b.z), 0.f) * ro;
            o.w = fmaxf(fmaf(acc.w, ri, b.w), 0.f) * ro;
            uint2 p = make_uint2(bf2_pack(o.x, o.y), bf2_pack(o.z, o.w));
            *(uint2*)(g_bufBh + (long)warp * 128 + lane * 4) = p;
        } else {
            o.x = fmaxf(fmaf(acc.x, ri, b.x), 0.f);
            o.y = fmaxf(fmaf(acc.y, ri, b.y), 0.f);
            o.z = fmaxf(fmaf(acc.z, ri, b.z), 0.f);
            o.w = fmaxf(fmaf(acc.w, ri, b.w), 0.f);
        }
    }

    if (FINAL) {
        *(float4*)&srow[w][lane * 4] = o;
        if (lane == 0) {
            bool w64 = (g_idx64 != 0);
            sgid[w] = active ? ldidx(gids, warp, w64) : -1;
        }
        __syncthreads();
        if (threadIdx.x < DIM) {
            int col = threadIdx.x;
            float* bucket = g_gsumB + (blockIdx.x & (NBUCK - 1)) * (NGRAPHS * DIM);
            int cur = sgid[0];
            float acc = srow[0][col];
#pragma unroll
            for (int r = 1; r < 8; r++) {
                int gr = sgid[r];
                float v = srow[r][col];
                if (gr == cur) {
                    acc += v;
                } else {
                    if (cur >= 0) atomicAdd(&bucket[cur * DIM + col], acc);
                    cur = gr; acc = v;
                }
            }
            if (cur >= 0) atomicAdd(&bucket[cur * DIM + col], acc);
        }
    }
}

// ---------------- 8. fold buckets -> g_gsum, then re-zero buckets ----------------
__global__ void k_gsum_reduce() {
    int i = blockIdx.x * blockDim.x + threadIdx.x;
    if (i < NGRAPHS * DIM) {
        float s = 0.f;
#pragma unroll 8
        for (int b = 0; b < NBUCK; b++) {
            s += g_gsumB[b * (NGRAPHS * DIM) + i];
            g_gsumB[b * (NGRAPHS * DIM) + i] = 0.0f;   // ready for next invocation
        }
        g_gsum[i] = s;
    }
}

// ---------------- 9. classifier head ----------------
__global__ void k_final(const float* __restrict__ Wc, const float* __restrict__ bc,
                        float* __restrict__ out) {
    int t = threadIdx.x;
    if (t >= NGRAPHS * NCLS) return;
    int g = t / NCLS, c = t % NCLS;
    float s = 0.f;
#pragma unroll 8
    for (int k = 0; k < 128; k++) s = fmaf(g_gsum[g * 128 + k], Wc[k * NCLS + c], s);
    float cnt = (float)max(g_gcnt[g], 1);
    out[t] = s / cnt + bc[c];
}

// ---------------- launch ----------------
extern "C" void kernel_launch(void* const* d_in, const int* in_sizes, int n_in,
                              void* d_out, int out_size) {
    const float* h   = (const float*)d_in[0];
    const void*  src = d_in[1];
    const void*  dst = d_in[2];
    const void*  gid = d_in[3];
    const float* W1  = (const float*)d_in[4];
    const float* b1  = (const float*)d_in[5];
    const float* W2  = (const float*)d_in[6];
    const float* b2  = (const float*)d_in[7];
    const float* Wc  = (const float*)d_in[8];
    const float* bc  = (const float*)d_in[9];
    float* out = (float*)d_out;

    const int M = NNODES;
    int gemmGrid = (M + 127) / 128;
    int spmmGrid = (M * 32 + 255) / 256;
    int degGrid  = (NEDGES / 4 + 255) / 256;   // 1563

    cudaFuncSetAttribute(k_mmagemm<1>, cudaFuncAttributeMaxDynamicSharedMemorySize, GEMM_DYN_SMEM);
    cudaFuncSetAttribute(k_mmagemm<2>, cudaFuncAttributeMaxDynamicSharedMemorySize, GEMM_DYN_SMEM);

    k_zero<<<512, 256>>>(src, W1, W2);                           // 1  (zero + detect + prepW)
    k_degrees<<<degGrid, 256>>>(src, dst, gid);                  // 2
    k_mmagemm<1><<<gemmGrid, 512, GEMM_DYN_SMEM>>>(h, M);        // 3
    k_scanA<<<NBLK, SCAN_B>>>();                                 // 4  <- profiled slot (scan cost)
    k_scanC<<<NBLK, SCAN_B>>>();                                 // 5
    k_scatter<<<1184, 256>>>(src, dst);                          // 6
    k_spmm<false><<<spmmGrid, 256>>>(b1, nullptr);               // 7
    k_mmagemm<2><<<gemmGrid, 512, GEMM_DYN_SMEM>>>(nullptr, M);  // 8
    k_spmm<true><<<spmmGrid, 256>>>(b2, gid);                    // 9
    k_gsum_reduce<<<32, 256>>>();                                // 10
    k_final<<<1, NGRAPHS * NCLS>>>(Wc, bc, out);                 // 11
}

// round 17
// speedup vs baseline: 1.0610x; 1.0058x over previous
#include <cuda_runtime.h>
#include <cuda_bf16.h>
#include <cstdint>

#define NNODES  100000
#define NEDGES  1600000
#define NGRAPHS 64
#define DIM     128
#define NCLS    10
#define SCAN_B  1024
#define NBLK    ((NNODES + SCAN_B - 1) / SCAN_B)   // 98
#define PB      136                                // smem pitch in bf16 (272B rows)
#define NBUCK   64

// ---------------- persistent device scratch ----------------
__device__ int   g_idx64;
__device__ int   g_scan_done;                      // last-block counter (self-resetting)
__device__ int   g_deg_out[NNODES];
__device__ int   g_deg_in[NNODES];
__device__ int   g_fill[NNODES];
__device__ int   g_rowptr[NNODES + 1];
__device__ int   g_csr[NEDGES];
__device__ int   g_bsum[NBLK];
__device__ int   g_boff[128];
__device__ __align__(16) __nv_bfloat16 g_bufAh[(size_t)NNODES * DIM];  // GEMM out (bf16)
__device__ __align__(16) __nv_bfloat16 g_bufBh[(size_t)NNODES * DIM];  // spmm1 out (bf16)
__device__ __align__(16) __nv_bfloat16 g_Whi[2][DIM * DIM];  // W transposed [n][k], hi
__device__ __align__(16) __nv_bfloat16 g_Wlo[2][DIM * DIM];  // W transposed [n][k], lo
__device__ float g_gsumB[NBUCK * NGRAPHS * DIM];   // bucketed partial sums (zeroed by reduce)
__device__ float g_gsum[NGRAPHS * DIM];
__device__ int   g_gcnt[NGRAPHS];

// ---------------- helpers ----------------
__device__ __forceinline__ int ldidx(const void* p, int i, bool w64) {
    if (w64) return (int)__ldg(((const long long*)p) + i);
    return __ldg(((const int*)p) + i);
}

__device__ __forceinline__ void mma16816(float* c, const uint32_t* a, uint32_t b0, uint32_t b1) {
    asm volatile(
        "mma.sync.aligned.m16n8k16.row.col.f32.bf16.bf16.f32 "
        "{%0,%1,%2,%3}, {%4,%5,%6,%7}, {%8,%9}, {%0,%1,%2,%3};"
        : "+f"(c[0]), "+f"(c[1]), "+f"(c[2]), "+f"(c[3])
        : "r"(a[0]), "r"(a[1]), "r"(a[2]), "r"(a[3]), "r"(b0), "r"(b1));
}

__device__ __forceinline__ void ldm_x4(uint32_t* r, uint32_t saddr) {
    asm volatile("ldmatrix.sync.aligned.m8n8.x4.shared.b16 {%0,%1,%2,%3}, [%4];"
                 : "=r"(r[0]), "=r"(r[1]), "=r"(r[2]), "=r"(r[3]) : "r"(saddr));
}

__device__ __forceinline__ uint32_t smem_u32(const void* p) {
    uint32_t a;
    asm("{ .reg .u64 t; cvta.to.shared.u64 t, %1; cvt.u32.u64 %0, t; }" : "=r"(a) : "l"(p));
    return a;
}

__device__ __forceinline__ uint32_t bf2_pack(float a, float b) {
    __nv_bfloat162 h;
    h.x = __float2bfloat16(a);
    h.y = __float2bfloat16(b);
    return *(uint32_t*)&h;
}

// accumulate 4 bf16 (one uint2) into a float4
__device__ __forceinline__ void bfacc(float4& a, uint2 u) {
    a.x += __uint_as_float(u.x << 16);
    a.y += __uint_as_float(u.x & 0xffff0000u);
    a.z += __uint_as_float(u.y << 16);
    a.w += __uint_as_float(u.y & 0xffff0000u);
}

// ---------------- 1. zero scratch + dtype detect (block 0) + prepW (blocks 0-127) ----------------
__global__ void k_zero(const void* src, const float* __restrict__ W1,
                       const float* __restrict__ W2) {
    if (blockIdx.x == 0) {
        __shared__ int any_nonzero;
        if (threadIdx.x == 0) any_nonzero = 0;
        __syncthreads();
        const unsigned int* p = (const unsigned int*)src;
        if (p[2 * threadIdx.x + 1] != 0u) atomicOr(&any_nonzero, 1);
        __syncthreads();
        if (threadIdx.x == 0) g_idx64 = (any_nonzero == 0) ? 1 : 0;
    }
    // prepW: 128 blocks x 256 threads cover 2*128*128 = 32768 elements
    if (blockIdx.x < 128) {
        int idx = blockIdx.x * 256 + threadIdx.x;
        int m = idx >> 14;
        int r = idx & 16383;
        int n = r & 127;               // consecutive n -> coalesced W read
        int k = r >> 7;
        const float* W = m ? W2 : W1;
        float w = __ldg(W + k * 128 + n);
        __nv_bfloat16 hi = __float2bfloat16(w);
        g_Whi[m][n * 128 + k] = hi;
        g_Wlo[m][n * 128 + k] = __float2bfloat16(w - __bfloat162float(hi));
    }
    int i = blockIdx.x * blockDim.x + threadIdx.x;
    int stride = gridDim.x * blockDim.x;
    for (int j = i; j < NNODES; j += stride) {
        g_deg_out[j] = 0;
        g_deg_in[j]  = 0;
    }
    if (i < NGRAPHS) g_gcnt[i] = 0;
}

// ---------------- 2. degree + graph-count histograms (4 edges/thread, MLP) ----------------
__global__ void k_degrees(const void* src, const void* dst, const void* gids) {
    bool w64 = (g_idx64 != 0);
    int t = blockIdx.x * blockDim.x + threadIdx.x;
    int e0 = t * 4;
    if (e0 + 4 <= NEDGES) {
        int s0, s1, s2, s3, d0, d1, d2, d3;
        if (w64) {
            const long long* sp = (const long long*)src + e0;
            const long long* dp = (const long long*)dst + e0;
            longlong2 a = __ldg((const longlong2*)sp);
            longlong2 b = __ldg((const longlong2*)(sp + 2));
            longlong2 c = __ldg((const longlong2*)dp);
            longlong2 d = __ldg((const longlong2*)(dp + 2));
            s0 = (int)a.x; s1 = (int)a.y; s2 = (int)b.x; s3 = (int)b.y;
            d0 = (int)c.x; d1 = (int)c.y; d2 = (int)d.x; d3 = (int)d.y;
        } else {
            int4 a = __ldg((const int4*)((const int*)src + e0));
            int4 c = __ldg((const int4*)((const int*)dst + e0));
            s0 = a.x; s1 = a.y; s2 = a.z; s3 = a.w;
            d0 = c.x; d1 = c.y; d2 = c.z; d3 = c.w;
        }
        atomicAdd(&g_deg_out[s0], 1);
        atomicAdd(&g_deg_out[s1], 1);
        atomicAdd(&g_deg_out[s2], 1);
        atomicAdd(&g_deg_out[s3], 1);
        atomicAdd(&g_deg_in[d0], 1);
        atomicAdd(&g_deg_in[d1], 1);
        atomicAdd(&g_deg_in[d2], 1);
        atomicAdd(&g_deg_in[d3], 1);
    } else {
        for (int e = e0; e < NEDGES; e++) {
            atomicAdd(&g_deg_out[ldidx(src, e, w64)], 1);
            atomicAdd(&g_deg_in[ldidx(dst, e, w64)], 1);
        }
    }
    if (t < NNODES) {
        int g = ldidx(gids, t, w64);
        atomicAdd(&g_gcnt[g], 1);
    }
}

// ---------------- 3-4. scan: block-local prefix + last-block computes block offsets ----------------
__global__ void __launch_bounds__(SCAN_B) k_scanA() {
    __shared__ int sh[SCAN_B];
    __shared__ int isLast;
    int tid = threadIdx.x;
    int i = blockIdx.x * SCAN_B + tid;
    int v = (i < NNODES) ? g_deg_in[i] : 0;
    sh[tid] = v;
    __syncthreads();
    for (int off = 1; off < SCAN_B; off <<= 1) {
        int t = (tid >= off) ? sh[tid - off] : 0;
        __syncthreads();
        sh[tid] += t;
        __syncthreads();
    }
    if (i < NNODES) g_rowptr[i] = sh[tid] - v;   // block-local exclusive prefix
    if (tid == SCAN_B - 1) g_bsum[blockIdx.x] = sh[tid];
    __threadfence();
    if (tid == 0) {
        int c = atomicAdd(&g_scan_done, 1);
        isLast = (c == gridDim.x - 1);
    }
    __syncthreads();
    if (isLast) {
        int bv = 0;
        if (tid < 128) bv = (tid < NBLK) ? g_bsum[tid] : 0;
        sh[tid] = bv;
        __syncthreads();
        for (int off = 1; off < 128; off <<= 1) {
            int t = (tid >= off && tid < 128) ? sh[tid - off] : 0;
            __syncthreads();
            if (tid < 128) sh[tid] += t;
            __syncthreads();
        }
        if (tid < 128) g_boff[tid] = sh[tid] - bv;
        if (tid == 0) g_scan_done = 0;           // reset for next invocation
    }
}

__global__ void __launch_bounds__(SCAN_B) k_scanC() {
    int tid = threadIdx.x;
    int i = blockIdx.x * SCAN_B + tid;
    if (i < NNODES) {
        int r = g_rowptr[i] + g_boff[blockIdx.x];
        g_rowptr[i] = r;
        g_fill[i]   = r;
    }
    if (i == 0) g_rowptr[NNODES] = NEDGES;
}

// ---------------- 5. CSR scatter ----------------
__global__ void k_scatter(const void* src, const void* dst) {
    bool w64 = (g_idx64 != 0);
    int i0 = blockIdx.x * blockDim.x + threadIdx.x;
    int stride = gridDim.x * blockDim.x;
    for (int e = i0; e < NEDGES; e += stride) {
        int d = ldidx(dst, e, w64);
        int s = ldidx(src, e, w64);
        int pos = atomicAdd(&g_fill[d], 1);
        g_csr[pos] = s;
    }
}

// ---------------- 6. mma.sync 2-term split GEMM (32x32 warp tiles, 2 CTA/SM) ----------------
#define SM_AHI 0
#define SM_BHI (128 * PB)
#define SM_BLO (2 * 128 * PB)
#define GEMM_DYN_SMEM (3 * 128 * PB * 2)   // 104448 bytes -> 2 CTAs/SM

template <int LAYER>
__global__ void __launch_bounds__(512, 2) k_mmagemm(const float* __restrict__ Aext, int M) {
    extern __shared__ __align__(16) __nv_bfloat16 sm[];

    __nv_bfloat16* __restrict__ C = g_bufAh;

    int tid = threadIdx.x;
    int wid = tid >> 5;
    int lane = tid & 31;
    int blockM = blockIdx.x * 128;

    if (LAYER == 1) {
#pragma unroll
        for (int it = 0; it < 8; it++) {
            int idx4 = tid + it * 512;
            int row = idx4 >> 5;
            int c4 = (idx4 & 31) * 4;
            int grow = blockM + row;
            float4 v = make_float4(0.f, 0.f, 0.f, 0.f);
            if (grow < M) {
                v = *(const float4*)(Aext + (long)grow * 128 + c4);
                float sc = rsqrtf((float)max(g_deg_out[grow], 1));
                v.x *= sc; v.y *= sc; v.z *= sc; v.w *= sc;
            }
            uint2 hu = make_uint2(bf2_pack(v.x, v.y), bf2_pack(v.z, v.w));
            *(uint2*)(sm + SM_AHI + row * PB + c4) = hu;
        }
    } else {
#pragma unroll
        for (int it = 0; it < 4; it++) {
            int idx = tid + it * 512;
            int row = idx >> 4;
            int c8 = (idx & 15) * 8;
            int grow = blockM + row;
            uint4 v = make_uint4(0u, 0u, 0u, 0u);
            if (grow < M) v = *(const uint4*)(g_bufBh + (long)grow * 128 + c8);
            *(uint4*)(sm + SM_AHI + row * PB + c8) = v;
        }
    }
    {
        const __nv_bfloat16* __restrict__ Wh = g_Whi[LAYER - 1];
        const __nv_bfloat16* __restrict__ Wl = g_Wlo[LAYER - 1];
#pragma unroll
        for (int it = 0; it < 4; it++) {
            int idx = tid + it * 512;
            int row = idx >> 4;
            int c8 = (idx & 15) * 8;
            uint4 hv = *(const uint4*)(Wh + row * 128 + c8);
            uint4 lv = *(const uint4*)(Wl + row * 128 + c8);
            *(uint4*)(sm + SM_BHI + row * PB + c8) = hv;
            *(uint4*)(sm + SM_BLO + row * PB + c8) = lv;
        }
    }
    __syncthreads();

    float acc[2][4][4];
#pragma unroll
    for (int mi = 0; mi < 2; mi++)
#pragma unroll
        for (int nt = 0; nt < 4; nt++)
#pragma unroll
            for (int j = 0; j < 4; j++) acc[mi][nt][j] = 0.0f;

    int warpRow = (wid >> 2) * 32;
    int warpCol = (wid & 3) * 32;
    int mtx  = lane >> 3;
    int lrow = lane & 7;

    uint32_t smbase = smem_u32(sm);
    uint32_t aoffElem = (uint32_t)((warpRow + lrow + (mtx & 1) * 8) * PB + (mtx >> 1) * 8);
    uint32_t boffRow  = (uint32_t)((warpCol + (mtx >> 1) * 8 + lrow) * PB + (mtx & 1) * 8);

#pragma unroll
    for (int ks = 0; ks < 8; ks++) {
        int kk = ks * 16;
        uint32_t a0[4], a1[4];
        ldm_x4(a0, smbase + (SM_AHI + aoffElem + kk) * 2);
        ldm_x4(a1, smbase + (SM_AHI + aoffElem + 16 * PB + kk) * 2);
#pragma unroll
        for (int np = 0; np < 2; np++) {
            uint32_t bhi[4], blo[4];
            uint32_t bo = boffRow + (uint32_t)(np * 16 * PB + kk);
            ldm_x4(bhi, smbase + (SM_BHI + bo) * 2);
            ldm_x4(blo, smbase + (SM_BLO + bo) * 2);
            mma16816(acc[0][2 * np],     a0, bhi[0], bhi[1]);
            mma16816(acc[0][2 * np],     a0, blo[0], blo[1]);
            mma16816(acc[0][2 * np + 1], a0, bhi[2], bhi[3]);
            mma16816(acc[0][2 * np + 1], a0, blo[2], blo[3]);
            mma16816(acc[1][2 * np],     a1, bhi[0], bhi[1]);
            mma16816(acc[1][2 * np],     a1, blo[0], blo[1]);
            mma16816(acc[1][2 * np + 1], a1, bhi[2], bhi[3]);
            mma16816(acc[1][2 * np + 1], a1, blo[2], blo[3]);
        }
    }

    int q2 = (lane & 3) * 2;
#pragma unroll
    for (int mi = 0; mi < 2; mi++) {
        int r0 = warpRow + mi * 16 + (lane >> 2);
        int growA = blockM + r0;
        int growB = growA + 8;
#pragma unroll
        for (int nt = 0; nt < 4; nt++) {
            int col = warpCol + nt * 8 + q2;
            if (growA < M) *(uint32_t*)(C + (long)growA * 128 + col) = bf2_pack(acc[mi][nt][0], acc[mi][nt][1]);
            if (growB < M) *(uint32_t*)(C + (long)growB * 128 + col) = bf2_pack(acc[mi][nt][2], acc[mi][nt][3]);
        }
    }
}

// ---------------- 7. SpMM (warp per dst row, bf16 gather) ----------------
template <bool FINAL>
__global__ void __launch_bounds__(256) k_spmm(const float* __restrict__ bias,
                                              const void* __restrict__ gids) {
    __shared__ float srow[8][DIM];
    __shared__ int   sgid[8];

    int warp = (blockIdx.x * blockDim.x + threadIdx.x) >> 5;
    int lane = threadIdx.x & 31;
    int w = (threadIdx.x >> 5);
    bool active = (warp < NNODES);

    float4 o = make_float4(0.f, 0.f, 0.f, 0.f);
    if (active) {
        int beg = g_rowptr[warp], end = g_rowptr[warp + 1];
        const __nv_bfloat16* __restrict__ T = g_bufAh;
        float4 acc0 = make_float4(0.f, 0.f, 0.f, 0.f);
        float4 acc1 = make_float4(0.f, 0.f, 0.f, 0.f);
        int e = beg;
        for (; e + 8 <= end; e += 8) {
            int s0 = g_csr[e],     s1 = g_csr[e + 1], s2 = g_csr[e + 2], s3 = g_csr[e + 3];
            int s4 = g_csr[e + 4], s5 = g_csr[e + 5], s6 = g_csr[e + 6], s7 = g_csr[e + 7];
            uint2 u0 = __ldg((const uint2*)(T + (long)s0 * 128 + lane * 4));
            uint2 u1 = __ldg((const uint2*)(T + (long)s1 * 128 + lane * 4));
            uint2 u2 = __ldg((const uint2*)(T + (long)s2 * 128 + lane * 4));
            uint2 u3 = __ldg((const uint2*)(T + (long)s3 * 128 + lane * 4));
            uint2 u4 = __ldg((const uint2*)(T + (long)s4 * 128 + lane * 4));
            uint2 u5 = __ldg((const uint2*)(T + (long)s5 * 128 + lane * 4));
            uint2 u6 = __ldg((const uint2*)(T + (long)s6 * 128 + lane * 4));
            uint2 u7 = __ldg((const uint2*)(T + (long)s7 * 128 + lane * 4));
            bfacc(acc0, u0); bfacc(acc0, u1); bfacc(acc0, u2); bfacc(acc0, u3);
            bfacc(acc1, u4); bfacc(acc1, u5); bfacc(acc1, u6); bfacc(acc1, u7);
        }
        for (; e + 4 <= end; e += 4) {
            int s0 = g_csr[e], s1 = g_csr[e + 1], s2 = g_csr[e + 2], s3 = g_csr[e + 3];
            uint2 u0 = __ldg((const uint2*)(T + (long)s0 * 128 + lane * 4));
            uint2 u1 = __ldg((const uint2*)(T + (long)s1 * 128 + lane * 4));
            uint2 u2 = __ldg((const uint2*)(T + (long)s2 * 128 + lane * 4));
            uint2 u3 = __ldg((const uint2*)(T + (long)s3 * 128 + lane * 4));
            bfacc(acc0, u0); bfacc(acc0, u1); bfacc(acc0, u2); bfacc(acc0, u3);
        }
        for (; e < end; e++) {
            int s = g_csr[e];
            uint2 u = __ldg((const uint2*)(T + (long)s * 128 + lane * 4));
            bfacc(acc1, u);
        }
        float4 acc = make_float4(acc0.x + acc1.x, acc0.y + acc1.y,
                                 acc0.z + acc1.z, acc0.w + acc1.w);
        float ri = rsqrtf((float)max(end - beg, 1));
        float4 b = *(const float4*)(bias + lane * 4);
        if (!FINAL) {
            float ro = rsqrtf((float)max(g_deg_out[warp], 1));
            o.x = fmaxf(fmaf(acc.x, ri, b.x), 0.f) * ro;
            o.y = fmaxf(fmaf(acc.y, ri, b.y), 0.f) * ro;
            o.z = fmaxf(fmaf(acc.z, ri, b.z), 0.f) * ro;
            o.w = fmaxf(fmaf(acc.w, ri, b.w), 0.f) * ro;
            uint2 p = make_uint2(bf2_pack(o.x, o.y), bf2_pack(o.z, o.w));
            *(uint2*)(g_bufBh + (long)warp * 128 + lane * 4) = p;
        } else {
            o.x = fmaxf(fmaf(acc.x, ri, b.x), 0.f);
            o.y = fmaxf(fmaf(acc.y, ri, b.y), 0.f);
            o.z = fmaxf(fmaf(acc.z, ri, b.z), 0.f);
            o.w = fmaxf(fmaf(acc.w, ri, b.w), 0.f);
        }
    }

    if (FINAL) {
        *(float4*)&srow[w][lane * 4] = o;
        if (lane == 0) {
            bool w64 = (g_idx64 != 0);
            sgid[w] = active ? ldidx(gids, warp, w64) : -1;
        }
        __syncthreads();
        if (threadIdx.x < DIM) {
            int col = threadIdx.x;
            float* bucket = g_gsumB + (blockIdx.x & (NBUCK - 1)) * (NGRAPHS * DIM);
            int cur = sgid[0];
            float acc = srow[0][col];
#pragma unroll
            for (int r = 1; r < 8; r++) {
                int gr = sgid[r];
                float v = srow[r][col];
                if (gr == cur) {
                    acc += v;
                } else {
                    if (cur >= 0) atomicAdd(&bucket[cur * DIM + col], acc);
                    cur = gr; acc = v;
                }
            }
            if (cur >= 0) atomicAdd(&bucket[cur * DIM + col], acc);
        }
    }
}

// ---------------- 8. fold buckets -> g_gsum, then re-zero buckets ----------------
__global__ void k_gsum_reduce() {
    int i = blockIdx.x * blockDim.x + threadIdx.x;
    if (i < NGRAPHS * DIM) {
        float s = 0.f;
#pragma unroll 8
        for (int b = 0; b < NBUCK; b++) {
            s += g_gsumB[b * (NGRAPHS * DIM) + i];
            g_gsumB[b * (NGRAPHS * DIM) + i] = 0.0f;
        }
        g_gsum[i] = s;
    }
}

// ---------------- 9. classifier head ----------------
__global__ void k_final(const float* __restrict__ Wc, const float* __restrict__ bc,
                        float* __restrict__ out) {
    int t = threadIdx.x;
    if (t >= NGRAPHS * NCLS) return;
    int g = t / NCLS, c = t % NCLS;
    float s = 0.f;
#pragma unroll 8
    for (int k = 0; k < 128; k++) s = fmaf(g_gsum[g * 128 + k], Wc[k * NCLS + c], s);
    float cnt = (float)max(g_gcnt[g], 1);
    out[t] = s / cnt + bc[c];
}

// ---------------- launch: fork graph-build branch parallel to GEMM1 ----------------
extern "C" void kernel_launch(void* const* d_in, const int* in_sizes, int n_in,
                              void* d_out, int out_size) {
    const float* h   = (const float*)d_in[0];
    const void*  src = d_in[1];
    const void*  dst = d_in[2];
    const void*  gid = d_in[3];
    const float* W1  = (const float*)d_in[4];
    const float* b1  = (const float*)d_in[5];
    const float* W2  = (const float*)d_in[6];
    const float* b2  = (const float*)d_in[7];
    const float* Wc  = (const float*)d_in[8];
    const float* bc  = (const float*)d_in[9];
    float* out = (float*)d_out;

    const int M = NNODES;
    int gemmGrid = (M + 127) / 128;
    int spmmGrid = (M * 32 + 255) / 256;
    int degGrid  = (NEDGES / 4 + 255) / 256;   // 1563

    cudaFuncSetAttribute(k_mmagemm<1>, cudaFuncAttributeMaxDynamicSharedMemorySize, GEMM_DYN_SMEM);
    cudaFuncSetAttribute(k_mmagemm<2>, cudaFuncAttributeMaxDynamicSharedMemorySize, GEMM_DYN_SMEM);

    // side stream + events for the fork/join (created per call; kernel_launch only
    // runs on the correctness/capture calls, replays re-execute the captured graph)
    cudaStream_t s2;
    cudaStreamCreateWithFlags(&s2, cudaStreamNonBlocking);
    cudaEvent_t evFork, evJoin;
    cudaEventCreateWithFlags(&evFork, cudaEventDisableTiming);
    cudaEventCreateWithFlags(&evJoin, cudaEventDisableTiming);

    k_zero<<<512, 256>>>(src, W1, W2);                           // 1  (zero + detect + prepW)
    k_degrees<<<degGrid, 256>>>(src, dst, gid);                  // 2

    // fork: graph-build branch on s2 (deg_in -> rowptr/fill -> csr)
    cudaEventRecord(evFork, 0);
    cudaStreamWaitEvent(s2, evFork, 0);
    k_scanA<<<NBLK, SCAN_B, 0, s2>>>();
    k_scanC<<<NBLK, SCAN_B, 0, s2>>>();
    k_scatter<<<1184, 256, 0, s2>>>(src, dst);
    cudaEventRecord(evJoin, s2);

    // main branch: GEMM1 (needs only deg_out + h + W) runs concurrently
    k_mmagemm<1><<<gemmGrid, 512, GEMM_DYN_SMEM>>>(h, M);

    // join: spmm1 needs both bufAh and csr
    cudaStreamWaitEvent(0, evJoin, 0);
    k_spmm<false><<<spmmGrid, 256>>>(b1, nullptr);
    k_mmagemm<2><<<gemmGrid, 512, GEMM_DYN_SMEM>>>(nullptr, M);
    k_spmm<true><<<spmmGrid, 256>>>(b2, gid);
    k_gsum_reduce<<<32, 256>>>();
    k_final<<<1, NGRAPHS * NCLS>>>(Wc, bc, out);
}